// round 1
// baseline (speedup 1.0000x reference)
#include <cuda_runtime.h>
#include <cuda_bf16.h>
#include <cstddef>

// ---------------------------------------------------------------------------
// Sparse 3D UNet forward (UNetV2).  One generic sparse-conv kernel:
//   out[i, cout] = epilogue( sum_k sum_cin feat[nbr[i,k], cin] * W[k,cin,cout] )
// epilogue: *scale + bias  (+resid)  -> relu  (+pair_reduce(red))
// ---------------------------------------------------------------------------

// Scratch pool for all intermediate feature maps (static device global: legal).
// 96M floats = 384 MB, far above worst-case (~30M floats needed).
__device__ float g_pool[96u * 1024u * 1024u];

template <int CIN, int COUT, int ROWS>
__global__ void __launch_bounds__(ROWS * 32)
spconv_kernel(const float* __restrict__ feat, int ldf,
              const int* __restrict__ nbr,
              const float* __restrict__ W,     // (27, CIN, COUT)
              const float* __restrict__ sb,    // scale[0..COUT), bias[COUT..2*COUT)
              const float* __restrict__ resid, int ldr,     // pre-relu add (or null)
              const float* __restrict__ red,   int ldred,   // post-relu pair-sum add (or null)
              float* __restrict__ out, int ldo, int N)
{
    constexpr int NACC = COUT / 32;
    __shared__ float sf[ROWS][CIN];

    const int w    = threadIdx.x >> 5;
    const int lane = threadIdx.x & 31;
    const int row  = blockIdx.x * ROWS + w;
    if (row >= N) return;

    float acc[NACC];
#pragma unroll
    for (int a = 0; a < NACC; ++a) acc[a] = 0.f;

    const int* nb = nbr + (size_t)row * 27;

#pragma unroll 1
    for (int k = 0; k < 27; ++k) {
        const int idx = nb[k];              // warp-uniform
        if (idx >= 0) {
            const float* fr = feat + (size_t)idx * ldf;
#pragma unroll
            for (int c = lane; c < CIN; c += 32) sf[w][c] = fr[c];
            __syncwarp();

            const float* wk = W + (size_t)k * CIN * COUT + lane;
#pragma unroll
            for (int cin = 0; cin < CIN; ++cin) {
                const float f = sf[w][cin];
#pragma unroll
                for (int a = 0; a < NACC; ++a)
                    acc[a] = fmaf(f, wk[cin * COUT + a * 32], acc[a]);
            }
            __syncwarp();
        }
    }

#pragma unroll
    for (int a = 0; a < NACC; ++a) {
        const int c = lane + a * 32;
        float v = acc[a] * sb[c] + sb[COUT + c];
        if (resid) v += resid[(size_t)row * ldr + c];
        v = fmaxf(v, 0.f);
        if (red)   v += red[(size_t)row * ldred + 2 * c]
                      + red[(size_t)row * ldred + 2 * c + 1];
        out[(size_t)row * ldo + c] = v;
    }
}

template <int CIN, int COUT>
static void conv_launch(const float* feat, int ldf, const int* nbr,
                        const float* W, const float* sb,
                        const float* resid, int ldr,
                        const float* red, int ldred,
                        float* out, int ldo, int N)
{
    constexpr int ROWS = 4;
    const int grid = (N + ROWS - 1) / ROWS;
    spconv_kernel<CIN, COUT, ROWS><<<grid, ROWS * 32>>>(
        feat, ldf, nbr, W, sb, resid, ldr, red, ldred, out, ldo, N);
}

extern "C" void kernel_launch(void* const* d_in, const int* in_sizes, int n_in,
                              void* d_out, int out_size)
{
    const float* voxel  = (const float*)d_in[0];
    const float* Win    = (const float*)d_in[1];
    const float* W32    = (const float*)d_in[2];
    const float* W64    = (const float*)d_in[3];
    const float* Wd3    = (const float*)d_in[4];
    const float* W6432  = (const float*)d_in[5];
    const float* W12864 = (const float*)d_in[6];
    const float* bn32   = (const float*)d_in[7];
    const float* bn64   = (const float*)d_in[8];
    const int* nbr1  = (const int*)d_in[9];
    const int* nbr2  = (const int*)d_in[10];
    const int* nbr3  = (const int*)d_in[11];
    const int* nbr4  = (const int*)d_in[12];
    const int* nbrd2 = (const int*)d_in[13];
    const int* nbrd3 = (const int*)d_in[14];
    const int* nbrd4 = (const int*)d_in[15];
    const int* nbri4 = (const int*)d_in[16];
    const int* nbri3 = (const int*)d_in[17];
    const int* nbri2 = (const int*)d_in[18];

    const int N1 = in_sizes[9]  / 27;
    const int N2 = in_sizes[10] / 27;
    const int N3 = in_sizes[11] / 27;
    const int N4 = in_sizes[12] / 27;

    float* pool = nullptr;
    cudaGetSymbolAddress((void**)&pool, g_pool);

    // Pool layout (float offsets), 256-float aligned.
    size_t o = 0;
    auto take = [&](size_t n) { size_t r = o; o += (n + 255) & ~(size_t)255; return r; };
    float* A    = pool + take((size_t)N1 * 32);
    float* X1   = pool + take((size_t)N1 * 32);
    float* cat1 = pool + take((size_t)N1 * 64);
    float* C    = pool + take((size_t)N2 * 32);
    float* Dm   = pool + take((size_t)N2 * 32);
    float* X2   = pool + take((size_t)N2 * 32);
    float* cat2 = pool + take((size_t)N2 * 64);
    float* Fm   = pool + take((size_t)N3 * 64);
    float* G    = pool + take((size_t)N3 * 64);
    float* X3   = pool + take((size_t)N3 * 64);
    float* cat3 = pool + take((size_t)N3 * 128);
    float* I    = pool + take((size_t)N4 * 64);
    float* J    = pool + take((size_t)N4 * 64);
    float* cat4 = pool + take((size_t)N4 * 128);

    float* outp = (float*)d_out;

    const size_t S32   = 27u * 32 * 32;
    const size_t S64   = 27u * 64 * 64;
    const size_t S6432 = 27u * 64 * 32;
    const size_t S1286 = 27u * 128 * 64;

    // ---- Encoder ----
    // x = block(voxel, nbr1, Win, bn32[0])
    conv_launch<4, 32>(voxel, 4, nbr1, Win, bn32 + 0 * 64, nullptr, 0, nullptr, 0, A, 32, N1);
    // x1 = block(x, nbr1, W32[0], bn32[1])
    conv_launch<32, 32>(A, 32, nbr1, W32 + 0 * S32, bn32 + 1 * 64, nullptr, 0, nullptr, 0, X1, 32, N1);
    // h = block(x1, nbrd2, W32[1], bn32[2])
    conv_launch<32, 32>(X1, 32, nbrd2, W32 + 1 * S32, bn32 + 2 * 64, nullptr, 0, nullptr, 0, C, 32, N2);
    // h = block(h, nbr2, W32[2], bn32[3])
    conv_launch<32, 32>(C, 32, nbr2, W32 + 2 * S32, bn32 + 3 * 64, nullptr, 0, nullptr, 0, Dm, 32, N2);
    // x2 = block(h, nbr2, W32[3], bn32[4])
    conv_launch<32, 32>(Dm, 32, nbr2, W32 + 3 * S32, bn32 + 4 * 64, nullptr, 0, nullptr, 0, X2, 32, N2);
    // h = block(x2, nbrd3, Wd3, bn64[0])
    conv_launch<32, 64>(X2, 32, nbrd3, Wd3, bn64 + 0 * 128, nullptr, 0, nullptr, 0, Fm, 64, N3);
    // h = block(h, nbr3, W64[0], bn64[1])
    conv_launch<64, 64>(Fm, 64, nbr3, W64 + 0 * S64, bn64 + 1 * 128, nullptr, 0, nullptr, 0, G, 64, N3);
    // x3 = block(h, nbr3, W64[1], bn64[2])
    conv_launch<64, 64>(G, 64, nbr3, W64 + 1 * S64, bn64 + 2 * 128, nullptr, 0, nullptr, 0, X3, 64, N3);
    // h = block(x3, nbrd4, W64[2], bn64[3])
    conv_launch<64, 64>(X3, 64, nbrd4, W64 + 2 * S64, bn64 + 3 * 128, nullptr, 0, nullptr, 0, I, 64, N4);
    // h = block(h, nbr4, W64[3], bn64[4])
    conv_launch<64, 64>(I, 64, nbr4, W64 + 3 * S64, bn64 + 4 * 128, nullptr, 0, nullptr, 0, J, 64, N4);
    // x4 = block(h, nbr4, W64[4], bn64[5])  -> cat4[:, :64]
    conv_launch<64, 64>(J, 64, nbr4, W64 + 4 * S64, bn64 + 5 * 128, nullptr, 0, nullptr, 0, cat4, 128, N4);

    // ---- Bottleneck: t = basic(x4, nbr4, W64[5], bn64[6], W64[6], bn64[7]) -> cat4[:,64:]
    conv_launch<64, 64>(cat4, 128, nbr4, W64 + 5 * S64, bn64 + 6 * 128, nullptr, 0, nullptr, 0, I, 64, N4);
    conv_launch<64, 64>(I, 64, nbr4, W64 + 6 * S64, bn64 + 7 * 128, cat4, 128, nullptr, 0, cat4 + 64, 128, N4);
    // x = block(cat4, nbr4, W12864[0], bn64[11]) + reduce(cat4, 64)
    conv_launch<128, 64>(cat4, 128, nbr4, W12864 + 0 * S1286, bn64 + 11 * 128, nullptr, 0, cat4, 128, J, 64, N4);

    // ---- Decoder level 3 ----
    // xu4 = block(x, nbri4, W64[7], bn64[8]) -> cat3[:, :64]
    conv_launch<64, 64>(J, 64, nbri4, W64 + 7 * S64, bn64 + 8 * 128, nullptr, 0, nullptr, 0, cat3, 128, N3);
    // t = basic(x3, nbr3, W64[8], bn64[9], W64[9], bn64[10]) -> cat3[:,64:]
    conv_launch<64, 64>(X3, 64, nbr3, W64 + 8 * S64, bn64 + 9 * 128, nullptr, 0, nullptr, 0, Fm, 64, N3);
    conv_launch<64, 64>(Fm, 64, nbr3, W64 + 9 * S64, bn64 + 10 * 128, X3, 64, nullptr, 0, cat3 + 64, 128, N3);
    // x = block(cat3, nbr3, W12864[1], bn64[12]) + reduce(cat3, 64)
    conv_launch<128, 64>(cat3, 128, nbr3, W12864 + 1 * S1286, bn64 + 12 * 128, nullptr, 0, cat3, 128, G, 64, N3);

    // ---- Decoder level 2 ----
    // xu3 = block(x, nbri3, W6432[0], bn32[11]) -> cat2[:, :32]
    conv_launch<64, 32>(G, 64, nbri3, W6432 + 0 * S6432, bn32 + 11 * 64, nullptr, 0, nullptr, 0, cat2, 64, N2);
    // t = basic(x2, nbr2, W32[4], bn32[5], W32[5], bn32[6]) -> cat2[:,32:]
    conv_launch<32, 32>(X2, 32, nbr2, W32 + 4 * S32, bn32 + 5 * 64, nullptr, 0, nullptr, 0, C, 32, N2);
    conv_launch<32, 32>(C, 32, nbr2, W32 + 5 * S32, bn32 + 6 * 64, X2, 32, nullptr, 0, cat2 + 32, 64, N2);
    // x = block(cat2, nbr2, W6432[1], bn32[12]) + reduce(cat2, 32)
    conv_launch<64, 32>(cat2, 64, nbr2, W6432 + 1 * S6432, bn32 + 12 * 64, nullptr, 0, cat2, 64, Dm, 32, N2);

    // ---- Decoder level 1 ----
    // xu2 = block(x, nbri2, W32[6], bn32[7]) -> cat1[:, :32]
    conv_launch<32, 32>(Dm, 32, nbri2, W32 + 6 * S32, bn32 + 7 * 64, nullptr, 0, nullptr, 0, cat1, 64, N1);
    // t = basic(x1, nbr1, W32[7], bn32[8], W32[8], bn32[9]) -> cat1[:,32:]
    conv_launch<32, 32>(X1, 32, nbr1, W32 + 7 * S32, bn32 + 8 * 64, nullptr, 0, nullptr, 0, A, 32, N1);
    conv_launch<32, 32>(A, 32, nbr1, W32 + 8 * S32, bn32 + 9 * 64, X1, 32, nullptr, 0, cat1 + 32, 64, N1);
    // x = block(cat1, nbr1, W6432[2], bn32[13]) + reduce(cat1, 32)
    conv_launch<64, 32>(cat1, 64, nbr1, W6432 + 2 * S6432, bn32 + 13 * 64, nullptr, 0, cat1, 64, A, 32, N1);

    // ---- Head: out = block(x, nbr1, W32[9], bn32[10]) ----
    conv_launch<32, 32>(A, 32, nbr1, W32 + 9 * S32, bn32 + 10 * 64, nullptr, 0, nullptr, 0, outp, 32, N1);
}

// round 2
// speedup vs baseline: 1.1935x; 1.1935x over previous
#include <cuda_runtime.h>
#include <cstddef>
#include <cstdint>

// ---------------------------------------------------------------------------
// Sparse 3D UNet forward.  Tiled-GEMM sparse conv:
//   out[i, cout] = epi( sum_k sum_cin feat[nbr[i,k], cin] * W[k,cin,cout] )
// Block: BM rows x COUT cols.  Thread tile: 8 rows x 4 couts, accumulated as
// packed f32x2 pairs (fma.rn.f32x2 -> 2x fp32 FMA throughput on sm_103a).
// ---------------------------------------------------------------------------

__device__ float g_pool[96u * 1024u * 1024u];   // 384 MB scratch (static: legal)

__device__ __forceinline__ unsigned long long pack2(float lo, float hi) {
    unsigned long long r;
    asm("mov.b64 %0, {%1,%2};" : "=l"(r) : "f"(lo), "f"(hi));
    return r;
}
__device__ __forceinline__ void unpack2(unsigned long long v, float& lo, float& hi) {
    asm("mov.b64 {%0,%1}, %2;" : "=f"(lo), "=f"(hi) : "l"(v));
}
__device__ __forceinline__ unsigned long long ffma2(unsigned long long a,
                                                    unsigned long long b,
                                                    unsigned long long c) {
    unsigned long long d;
    asm("fma.rn.f32x2 %0, %1, %2, %3;" : "=l"(d) : "l"(a), "l"(b), "l"(c));
    return d;
}

template <int CIN, int COUT>
__global__ void __launch_bounds__(128)
spconv_gemm(const float* __restrict__ feat, int ldf,
            const int* __restrict__ nbr,
            const float* __restrict__ W,      // (27, CIN, COUT)
            const float* __restrict__ sb,     // scale[COUT], bias[COUT]
            const float* __restrict__ resid, int ldr,
            const float* __restrict__ red,   int ldred,
            float* __restrict__ out, int ldo, int N)
{
    constexpr int TN = 4;
    constexpr int TM = 8;
    constexpr int TX = COUT / TN;     // 8 (COUT=32) or 16 (COUT=64)
    constexpr int TY = 128 / TX;      // 16 or 8
    constexpr int BM = TY * TM;       // 128 or 64

    __shared__ int   snbr[27][BM];
    __shared__ float sfeat[BM][CIN];
    __shared__ float sW[CIN][COUT];
    __shared__ int   khit[27];

    const int tid  = threadIdx.x;
    const int tx   = tid % TX;
    const int ty   = tid / TX;
    const int row0 = blockIdx.x * BM;

    // Stage neighbor indices (coalesced read of [row][27])
    for (int e = tid; e < BM * 27; e += 128) {
        int r = e / 27, k = e % 27;
        int g = row0 + r;
        snbr[k][r] = (g < N) ? nbr[(size_t)g * 27 + k] : -1;
    }
    __syncthreads();
    if (tid < 27) {
        int h = 0;
        for (int r = 0; r < BM && !h; ++r) h = (snbr[tid][r] >= 0);
        khit[tid] = h;
    }
    __syncthreads();

    unsigned long long a01[TM], a23[TM];
#pragma unroll
    for (int i = 0; i < TM; ++i) { a01[i] = 0ull; a23[i] = 0ull; }

    for (int k = 0; k < 27; ++k) {
        if (!khit[k]) continue;

        // Stage gathered features: sfeat[r][c] (zero rows for missing nbrs)
#pragma unroll
        for (int u = tid; u < BM * CIN / 4; u += 128) {
            int r  = u / (CIN / 4);
            int c4 = u % (CIN / 4);
            int idx = snbr[k][r];
            float4 v = make_float4(0.f, 0.f, 0.f, 0.f);
            if (idx >= 0)
                v = *(const float4*)(feat + (size_t)idx * ldf + c4 * 4);
            *(float4*)(&sfeat[r][c4 * 4]) = v;
        }
        // Stage W[k]
#pragma unroll
        for (int u = tid; u < CIN * COUT / 4; u += 128) {
            int c  = u / (COUT / 4);
            int n4 = u % (COUT / 4);
            *(float4*)(&sW[c][n4 * 4]) =
                *(const float4*)(W + (size_t)k * CIN * COUT + (size_t)c * COUT + n4 * 4);
        }
        __syncthreads();

#pragma unroll 4
        for (int cin = 0; cin < CIN; ++cin) {
            float4 wv = *(const float4*)(&sW[cin][tx * TN]);
            unsigned long long w01 = pack2(wv.x, wv.y);
            unsigned long long w23 = pack2(wv.z, wv.w);
#pragma unroll
            for (int i = 0; i < TM; ++i) {
                float f = sfeat[ty * TM + i][cin];
                unsigned long long ff = pack2(f, f);
                a01[i] = ffma2(ff, w01, a01[i]);
                a23[i] = ffma2(ff, w23, a23[i]);
            }
        }
        __syncthreads();
    }

    // Epilogue: *scale + bias (+resid) -> relu (+pair-reduce)
    float sc[TN], bi[TN];
#pragma unroll
    for (int j = 0; j < TN; ++j) {
        sc[j] = sb[tx * TN + j];
        bi[j] = sb[COUT + tx * TN + j];
    }

#pragma unroll
    for (int i = 0; i < TM; ++i) {
        int r = row0 + ty * TM + i;
        if (r >= N) continue;
        float v[4];
        unpack2(a01[i], v[0], v[1]);
        unpack2(a23[i], v[2], v[3]);
#pragma unroll
        for (int j = 0; j < TN; ++j) v[j] = v[j] * sc[j] + bi[j];
        if (resid) {
            float4 rr = *(const float4*)(resid + (size_t)r * ldr + tx * TN);
            v[0] += rr.x; v[1] += rr.y; v[2] += rr.z; v[3] += rr.w;
        }
#pragma unroll
        for (int j = 0; j < TN; ++j) v[j] = fmaxf(v[j], 0.f);
        if (red) {
            float4 ra = *(const float4*)(red + (size_t)r * ldred + 2 * tx * TN);
            float4 rb = *(const float4*)(red + (size_t)r * ldred + 2 * tx * TN + 4);
            v[0] += ra.x + ra.y; v[1] += ra.z + ra.w;
            v[2] += rb.x + rb.y; v[3] += rb.z + rb.w;
        }
        *(float4*)(out + (size_t)r * ldo + tx * TN) = make_float4(v[0], v[1], v[2], v[3]);
    }
}

template <int CIN, int COUT>
static void conv_launch(const float* feat, int ldf, const int* nbr,
                        const float* W, const float* sb,
                        const float* resid, int ldr,
                        const float* red, int ldred,
                        float* out, int ldo, int N)
{
    constexpr int BM = (COUT == 32) ? 128 : 64;
    const int grid = (N + BM - 1) / BM;
    spconv_gemm<CIN, COUT><<<grid, 128>>>(
        feat, ldf, nbr, W, sb, resid, ldr, red, ldred, out, ldo, N);
}

extern "C" void kernel_launch(void* const* d_in, const int* in_sizes, int n_in,
                              void* d_out, int out_size)
{
    const float* voxel  = (const float*)d_in[0];
    const float* Win    = (const float*)d_in[1];
    const float* W32    = (const float*)d_in[2];
    const float* W64    = (const float*)d_in[3];
    const float* Wd3    = (const float*)d_in[4];
    const float* W6432  = (const float*)d_in[5];
    const float* W12864 = (const float*)d_in[6];
    const float* bn32   = (const float*)d_in[7];
    const float* bn64   = (const float*)d_in[8];
    const int* nbr1  = (const int*)d_in[9];
    const int* nbr2  = (const int*)d_in[10];
    const int* nbr3  = (const int*)d_in[11];
    const int* nbr4  = (const int*)d_in[12];
    const int* nbrd2 = (const int*)d_in[13];
    const int* nbrd3 = (const int*)d_in[14];
    const int* nbrd4 = (const int*)d_in[15];
    const int* nbri4 = (const int*)d_in[16];
    const int* nbri3 = (const int*)d_in[17];
    const int* nbri2 = (const int*)d_in[18];

    const int N1 = in_sizes[9]  / 27;
    const int N2 = in_sizes[10] / 27;
    const int N3 = in_sizes[11] / 27;
    const int N4 = in_sizes[12] / 27;

    float* pool = nullptr;
    cudaGetSymbolAddress((void**)&pool, g_pool);

    size_t o = 0;
    auto take = [&](size_t n) { size_t r = o; o += (n + 255) & ~(size_t)255; return r; };
    float* A    = pool + take((size_t)N1 * 32);
    float* X1   = pool + take((size_t)N1 * 32);
    float* cat1 = pool + take((size_t)N1 * 64);
    float* C    = pool + take((size_t)N2 * 32);
    float* Dm   = pool + take((size_t)N2 * 32);
    float* X2   = pool + take((size_t)N2 * 32);
    float* cat2 = pool + take((size_t)N2 * 64);
    float* Fm   = pool + take((size_t)N3 * 64);
    float* G    = pool + take((size_t)N3 * 64);
    float* X3   = pool + take((size_t)N3 * 64);
    float* cat3 = pool + take((size_t)N3 * 128);
    float* I    = pool + take((size_t)N4 * 64);
    float* J    = pool + take((size_t)N4 * 64);
    float* cat4 = pool + take((size_t)N4 * 128);

    float* outp = (float*)d_out;

    const size_t S32   = 27u * 32 * 32;
    const size_t S64   = 27u * 64 * 64;
    const size_t S6432 = 27u * 64 * 32;
    const size_t S1286 = 27u * 128 * 64;

    // ---- Encoder ----
    conv_launch<4, 32>(voxel, 4, nbr1, Win, bn32 + 0 * 64, nullptr, 0, nullptr, 0, A, 32, N1);
    conv_launch<32, 32>(A, 32, nbr1, W32 + 0 * S32, bn32 + 1 * 64, nullptr, 0, nullptr, 0, X1, 32, N1);
    conv_launch<32, 32>(X1, 32, nbrd2, W32 + 1 * S32, bn32 + 2 * 64, nullptr, 0, nullptr, 0, C, 32, N2);
    conv_launch<32, 32>(C, 32, nbr2, W32 + 2 * S32, bn32 + 3 * 64, nullptr, 0, nullptr, 0, Dm, 32, N2);
    conv_launch<32, 32>(Dm, 32, nbr2, W32 + 3 * S32, bn32 + 4 * 64, nullptr, 0, nullptr, 0, X2, 32, N2);
    conv_launch<32, 64>(X2, 32, nbrd3, Wd3, bn64 + 0 * 128, nullptr, 0, nullptr, 0, Fm, 64, N3);
    conv_launch<64, 64>(Fm, 64, nbr3, W64 + 0 * S64, bn64 + 1 * 128, nullptr, 0, nullptr, 0, G, 64, N3);
    conv_launch<64, 64>(G, 64, nbr3, W64 + 1 * S64, bn64 + 2 * 128, nullptr, 0, nullptr, 0, X3, 64, N3);
    conv_launch<64, 64>(X3, 64, nbrd4, W64 + 2 * S64, bn64 + 3 * 128, nullptr, 0, nullptr, 0, I, 64, N4);
    conv_launch<64, 64>(I, 64, nbr4, W64 + 3 * S64, bn64 + 4 * 128, nullptr, 0, nullptr, 0, J, 64, N4);
    conv_launch<64, 64>(J, 64, nbr4, W64 + 4 * S64, bn64 + 5 * 128, nullptr, 0, nullptr, 0, cat4, 128, N4);

    // ---- Bottleneck ----
    conv_launch<64, 64>(cat4, 128, nbr4, W64 + 5 * S64, bn64 + 6 * 128, nullptr, 0, nullptr, 0, I, 64, N4);
    conv_launch<64, 64>(I, 64, nbr4, W64 + 6 * S64, bn64 + 7 * 128, cat4, 128, nullptr, 0, cat4 + 64, 128, N4);
    conv_launch<128, 64>(cat4, 128, nbr4, W12864 + 0 * S1286, bn64 + 11 * 128, nullptr, 0, cat4, 128, J, 64, N4);

    // ---- Decoder level 3 ----
    conv_launch<64, 64>(J, 64, nbri4, W64 + 7 * S64, bn64 + 8 * 128, nullptr, 0, nullptr, 0, cat3, 128, N3);
    conv_launch<64, 64>(X3, 64, nbr3, W64 + 8 * S64, bn64 + 9 * 128, nullptr, 0, nullptr, 0, Fm, 64, N3);
    conv_launch<64, 64>(Fm, 64, nbr3, W64 + 9 * S64, bn64 + 10 * 128, X3, 64, nullptr, 0, cat3 + 64, 128, N3);
    conv_launch<128, 64>(cat3, 128, nbr3, W12864 + 1 * S1286, bn64 + 12 * 128, nullptr, 0, cat3, 128, G, 64, N3);

    // ---- Decoder level 2 ----
    conv_launch<64, 32>(G, 64, nbri3, W6432 + 0 * S6432, bn32 + 11 * 64, nullptr, 0, nullptr, 0, cat2, 64, N2);
    conv_launch<32, 32>(X2, 32, nbr2, W32 + 4 * S32, bn32 + 5 * 64, nullptr, 0, nullptr, 0, C, 32, N2);
    conv_launch<32, 32>(C, 32, nbr2, W32 + 5 * S32, bn32 + 6 * 64, X2, 32, nullptr, 0, cat2 + 32, 64, N2);
    conv_launch<64, 32>(cat2, 64, nbr2, W6432 + 1 * S6432, bn32 + 12 * 64, nullptr, 0, cat2, 64, Dm, 32, N2);

    // ---- Decoder level 1 ----
    conv_launch<32, 32>(Dm, 32, nbri2, W32 + 6 * S32, bn32 + 7 * 64, nullptr, 0, nullptr, 0, cat1, 64, N1);
    conv_launch<32, 32>(X1, 32, nbr1, W32 + 7 * S32, bn32 + 8 * 64, nullptr, 0, nullptr, 0, A, 32, N1);
    conv_launch<32, 32>(A, 32, nbr1, W32 + 8 * S32, bn32 + 9 * 64, X1, 32, nullptr, 0, cat1 + 32, 64, N1);
    conv_launch<64, 32>(cat1, 64, nbr1, W6432 + 2 * S6432, bn32 + 13 * 64, nullptr, 0, cat1, 64, A, 32, N1);

    // ---- Head ----
    conv_launch<32, 32>(A, 32, nbr1, W32 + 9 * S32, bn32 + 10 * 64, nullptr, 0, nullptr, 0, outp, 32, N1);
}